// round 13
// baseline (speedup 1.0000x reference)
#include <cuda_runtime.h>
#include <cuda_fp16.h>
#include <cstdint>

#define H_DIM 4096
#define I_DIM 14336
#define M_DIM 8192   // B*S
#define BSQ   128

// ---------------- static device scratch ----------------
__device__ __align__(16) __half d_x16[(size_t)M_DIM * H_DIM];   // x fp16 [M,H] K-major
__device__ __align__(16) __half d_w0t[(size_t)I_DIM * H_DIM];   // W0^T [I,H] K-major
__device__ __align__(16) __half d_w1t[(size_t)I_DIM * H_DIM];   // W1^T [I,H]
__device__ __align__(16) __half d_w2t[(size_t)H_DIM * I_DIM];   // W2^T [H,I] (x64)
__device__ __align__(16) __half d_h16[(size_t)M_DIM * I_DIM];   // h/64 fp16 [M,I]

// ---------------- PTX helpers ----------------
__device__ __forceinline__ uint32_t smem_u32(const void* p) {
    uint32_t a;
    asm("{ .reg .u64 t; cvta.to.shared.u64 t, %1; cvt.u32.u64 %0, t; }" : "=r"(a) : "l"(p));
    return a;
}
#define CP16(s, g)   asm volatile("cp.async.cg.shared.global [%0], [%1], 16;" :: "r"(s), "l"(g))
#define CP_COMMIT()  asm volatile("cp.async.commit_group;" ::: "memory")
template<int N> __device__ __forceinline__ void cp_wait() {
    asm volatile("cp.async.wait_group %0;" :: "n"(N) : "memory");
}
#define LDSM4(r0, r1, r2, r3, a) \
    asm volatile("ldmatrix.sync.aligned.m8n8.x4.shared.b16 {%0,%1,%2,%3}, [%4];" \
        : "=r"(r0), "=r"(r1), "=r"(r2), "=r"(r3) : "r"(a))
#define MMA16816(c0, c1, c2, c3, a0, a1, a2, a3, b0, b1) \
    asm volatile("mma.sync.aligned.m16n8k16.row.col.f32.f16.f16.f32 " \
        "{%0,%1,%2,%3}, {%4,%5,%6,%7}, {%8,%9}, {%0,%1,%2,%3};" \
        : "+f"(c0), "+f"(c1), "+f"(c2), "+f"(c3) \
        : "r"(a0), "r"(a1), "r"(a2), "r"(a3), "r"(b0), "r"(b1))

// ---------------- prologue: x fp32 -> fp16 ----------------
__global__ void convert_x_kernel(const float* __restrict__ x) {
    size_t base = ((size_t)blockIdx.x * blockDim.x + threadIdx.x) * 4;
    if (base >= (size_t)M_DIM * H_DIM) return;
    float4 v = *reinterpret_cast<const float4*>(x + base);
    __half2* o = reinterpret_cast<__half2*>(d_x16 + base);
    o[0] = __floats2half2_rn(v.x, v.y);
    o[1] = __floats2half2_rn(v.z, v.w);
}

// ---------------- dequant + transpose: w[K,N] int32 -> out[N,K] fp16 ----------------
// tile stride 73 halves: 8-row stride = 292 words = 4 (mod 32) -> conflict-free
__global__ __launch_bounds__(256)
void dequantT_kernel(const int* __restrict__ w, const float* __restrict__ s,
                     __half* __restrict__ out, int Kd, int Nd, float mult) {
    __shared__ __half tile[64][73];
    const int n0 = blockIdx.x * 64, k0 = blockIdx.y * 64;
    const int tid = threadIdx.x;
    const int sr = k0 / BSQ;
#pragma unroll
    for (int i = 0; i < 4; i++) {
        int v = tid + i * 256;
        int r = v >> 4, c4 = (v & 15) * 4;
        int4   wv = *reinterpret_cast<const int4*>(w + (size_t)(k0 + r) * Nd + n0 + c4);
        float4 sv = *reinterpret_cast<const float4*>(s + (size_t)sr * Nd + n0 + c4);
        tile[r][c4 + 0] = __float2half_rn((float)wv.x * sv.x * mult);
        tile[r][c4 + 1] = __float2half_rn((float)wv.y * sv.y * mult);
        tile[r][c4 + 2] = __float2half_rn((float)wv.z * sv.z * mult);
        tile[r][c4 + 3] = __float2half_rn((float)wv.w * sv.w * mult);
    }
    __syncthreads();
#pragma unroll
    for (int i = 0; i < 2; i++) {
        int v = tid + i * 256;
        int nr = v >> 3, kc = (v & 7) * 8;
        __align__(16) __half tmp[8];
#pragma unroll
        for (int e = 0; e < 8; e++) tmp[e] = tile[kc + e][nr];
        *reinterpret_cast<uint4*>(out + (size_t)(n0 + nr) * Kd + k0 + kc) =
            *reinterpret_cast<const uint4*>(tmp);
    }
}

// =====================================================================================
// GEMM1 fused: 256 thr, 2 CTAs/SM. CTA 128m x 64n. Warps 0-3 gate, 4-7 up (64x32 tiles).
// m-major CTA order: A (67MB) stays L2-resident for the whole sweep; each weight strip
// read from DRAM exactly once. 3 stages x 32KB. Epilogue: smem exchange + silu -> fp16.
// =====================================================================================
__global__ __launch_bounds__(256, 2)
void gemm1_fused(const __half* __restrict__ A, const __half* __restrict__ B0,
                 const __half* __restrict__ B1, __half* __restrict__ Hout) {
    constexpr int K = H_DIM, N = I_DIM, STAGE = 32768, STAGES = 3;
    extern __shared__ char smem[];
    const uint32_t sbase = smem_u32(smem);
    const int tid = threadIdx.x, wid = tid >> 5, lane = tid & 31;
    const int t = wid >> 2;                  // 0=gate, 1=up
    const int w = wid & 3, wm = w & 1, wn = w >> 1;
    const int row_in = lane & 7, sel = lane >> 3;

    // m-major ordering: consecutive CTAs sweep m within one n-strip
    const int m0 = (blockIdx.x & 63) << 7;   // 64 m-tiles
    const int n0 = (blockIdx.x >> 6) << 6;   // 224 n-strips

    float acc[4][2][2][4];
#pragma unroll
    for (int mi = 0; mi < 4; mi++)
#pragma unroll
        for (int p = 0; p < 2; p++)
#pragma unroll
            for (int jj = 0; jj < 2; jj++)
#pragma unroll
                for (int e = 0; e < 4; e++) acc[mi][p][jj][e] = 0.0f;

    const char* Ab  = (const char*)(A  + (size_t)m0 * K);
    const char* B0b = (const char*)(B0 + (size_t)n0 * K);
    const char* B1b = (const char*)(B1 + (size_t)n0 * K);
    const size_t rowb = (size_t)K * 2;

    auto load_stage = [&](int c, int slot) {
        const uint32_t sb = sbase + slot * STAGE;
        const size_t koff = (size_t)c * 128;
#pragma unroll
        for (int j = 0; j < 4; j++) {
            int v = tid + j * 256, r = v >> 3, cs = v & 7, csw = cs ^ (r & 7);
            CP16(sb + r * 128 + csw * 16, Ab + (size_t)r * rowb + koff + cs * 16);
        }
#pragma unroll
        for (int j = 0; j < 4; j++) {
            int v = tid + j * 256, r = v >> 3, cs = v & 7, csw = cs ^ (r & 7);
            const char* src = ((r < 64) ? B0b + (size_t)r * rowb
                                        : B1b + (size_t)(r - 64) * rowb) + koff + cs * 16;
            CP16(sb + 16384 + r * 128 + csw * 16, src);
        }
    };

    const int NCH = K >> 6;   // 64
#pragma unroll
    for (int c = 0; c < STAGES - 1; c++) { load_stage(c, c); CP_COMMIT(); }

    const int a_row_base = wm * 64 + ((sel & 1) << 3) + row_in;
    const int a_c16_add  = sel >> 1;
    const int b_row_base = t * 64 + wn * 32 + ((sel >> 1) << 3) + row_in;
    const int b_c16_add  = sel & 1;

    int sc = 0, sl = STAGES - 1;
    for (int c = 0; c < NCH; c++) {
        cp_wait<STAGES - 2>();
        __syncthreads();
        const int lc = c + STAGES - 1;
        if (lc < NCH) load_stage(lc, sl);
        CP_COMMIT();
        if (++sl == STAGES) sl = 0;

        const uint32_t sb = sbase + sc * STAGE;
        if (++sc == STAGES) sc = 0;
#pragma unroll
        for (int ks = 0; ks < 4; ks++) {
            uint32_t a[4][4], b[2][4];
#pragma unroll
            for (int mi = 0; mi < 4; mi++) {
                int r = a_row_base + mi * 16;
                int c16 = ks * 2 + a_c16_add;
                uint32_t ad = sb + r * 128 + (((uint32_t)(c16 ^ (r & 7))) << 4);
                LDSM4(a[mi][0], a[mi][1], a[mi][2], a[mi][3], ad);
            }
#pragma unroll
            for (int p = 0; p < 2; p++) {
                int r = b_row_base + p * 16;
                int c16 = ks * 2 + b_c16_add;
                uint32_t bd = sb + 16384 + r * 128 + (((uint32_t)(c16 ^ (r & 7))) << 4);
                LDSM4(b[p][0], b[p][1], b[p][2], b[p][3], bd);
            }
#pragma unroll
            for (int p = 0; p < 2; p++)
#pragma unroll
                for (int mi = 0; mi < 4; mi++) {
                    float* c0 = acc[mi][p][0];
                    float* c1 = acc[mi][p][1];
                    MMA16816(c0[0], c0[1], c0[2], c0[3],
                             a[mi][0], a[mi][1], a[mi][2], a[mi][3], b[p][0], b[p][1]);
                    MMA16816(c1[0], c1[1], c1[2], c1[3],
                             a[mi][0], a[mi][1], a[mi][2], a[mi][3], b[p][2], b[p][3]);
                }
        }
    }

    // ---- epilogue: up warps publish 128x64 fp32 (stride 68), gate warps fuse ----
    cp_wait<0>();
    __syncthreads();
    constexpr int XS = 68;
    float* xch = (float*)smem;
    const int gid = lane >> 2, cpair = (lane & 3) * 2;
    if (t == 1) {
#pragma unroll
        for (int mi = 0; mi < 4; mi++)
#pragma unroll
            for (int p = 0; p < 2; p++)
#pragma unroll
                for (int jj = 0; jj < 2; jj++) {
                    int rr = wm * 64 + mi * 16 + gid;
                    int cc = wn * 32 + p * 16 + jj * 8 + cpair;
                    const float* d = acc[mi][p][jj];
                    *reinterpret_cast<float2*>(xch + rr * XS + cc) = make_float2(d[0], d[1]);
                    *reinterpret_cast<float2*>(xch + (rr + 8) * XS + cc) = make_float2(d[2], d[3]);
                }
    }
    __syncthreads();
    if (t == 0) {
#pragma unroll
        for (int mi = 0; mi < 4; mi++)
#pragma unroll
            for (int p = 0; p < 2; p++)
#pragma unroll
                for (int jj = 0; jj < 2; jj++) {
                    int rr = wm * 64 + mi * 16 + gid;
                    int cc = wn * 32 + p * 16 + jj * 8 + cpair;
                    const float* g = acc[mi][p][jj];
                    float2 u01 = *reinterpret_cast<const float2*>(xch + rr * XS + cc);
                    float2 u23 = *reinterpret_cast<const float2*>(xch + (rr + 8) * XS + cc);
                    float h0 = g[0] / (1.0f + __expf(-g[0])) * u01.x * 0.015625f;
                    float h1 = g[1] / (1.0f + __expf(-g[1])) * u01.y * 0.015625f;
                    float h2 = g[2] / (1.0f + __expf(-g[2])) * u23.x * 0.015625f;
                    float h3 = g[3] / (1.0f + __expf(-g[3])) * u23.y * 0.015625f;
                    *reinterpret_cast<__half2*>(Hout + (size_t)(m0 + rr) * N + n0 + cc) =
                        __floats2half2_rn(h0, h1);
                    *reinterpret_cast<__half2*>(Hout + (size_t)(m0 + rr + 8) * N + n0 + cc) =
                        __floats2half2_rn(h2, h3);
                }
    }
}

// =====================================================================================
// GEMM2: 256 thr, 2 CTAs/SM. CTA 128m x 128n, warps 2x4 of 64x32. out fp32. GROUP_M=16.
// =====================================================================================
__global__ __launch_bounds__(256, 2)
void gemm2_plain(const __half* __restrict__ A, const __half* __restrict__ B,
                 float* __restrict__ Cout) {
    constexpr int K = I_DIM, N = H_DIM, STAGE = 32768, STAGES = 3;
    extern __shared__ char smem[];
    const uint32_t sbase = smem_u32(smem);
    const int tid = threadIdx.x, wid = tid >> 5, lane = tid & 31;
    const int wm = wid & 1, wn = wid >> 1;
    const int row_in = lane & 7, sel = lane >> 3;

    const int per_band = 16 * (N >> 7);
    const int band = blockIdx.x / per_band, rem = blockIdx.x % per_band;
    const int m0 = (band * 16 + (rem & 15)) << 7;
    const int n0 = (rem >> 4) << 7;

    float acc[4][2][2][4];
#pragma unroll
    for (int mi = 0; mi < 4; mi++)
#pragma unroll
        for (int p = 0; p < 2; p++)
#pragma unroll
            for (int jj = 0; jj < 2; jj++)
#pragma unroll
                for (int e = 0; e < 4; e++) acc[mi][p][jj][e] = 0.0f;

    const char* Ab = (const char*)(A + (size_t)m0 * K);
    const char* Bb = (const char*)(B + (size_t)n0 * K);
    const size_t rowb = (size_t)K * 2;

    auto load_stage = [&](int c, int slot) {
        const uint32_t sb = sbase + slot * STAGE;
        const size_t koff = (size_t)c * 128;
#pragma unroll
        for (int j = 0; j < 4; j++) {
            int v = tid + j * 256, r = v >> 3, cs = v & 7, csw = cs ^ (r & 7);
            CP16(sb + r * 128 + csw * 16, Ab + (size_t)r * rowb + koff + cs * 16);
        }
#pragma unroll
        for (int j = 0; j < 4; j++) {
            int v = tid + j * 256, r = v >> 3, cs = v & 7, csw = cs ^ (r & 7);
            CP16(sb + 16384 + r * 128 + csw * 16, Bb + (size_t)r * rowb + koff + cs * 16);
        }
    };

    const int NCH = K >> 6;   // 224
#pragma unroll
    for (int c = 0; c < STAGES - 1; c++) { load_stage(c, c); CP_COMMIT(); }

    const int a_row_base = wm * 64 + ((sel & 1) << 3) + row_in;
    const int a_c16_add  = sel >> 1;
    const int b_row_base = wn * 32 + ((sel >> 1) << 3) + row_in;
    const int b_c16_add  = sel & 1;

    int sc = 0, sl = STAGES - 1;
    for (int c = 0; c < NCH; c++) {
        cp_wait<STAGES - 2>();
        __syncthreads();
        const int lc = c + STAGES - 1;
        if (lc < NCH) load_stage(lc, sl);
        CP_COMMIT();
        if (++sl == STAGES) sl = 0;

        const uint32_t sb = sbase + sc * STAGE;
        if (++sc == STAGES) sc = 0;
#pragma unroll
        for (int ks = 0; ks < 4; ks++) {
            uint32_t a[4][4], b[2][4];
#pragma unroll
            for (int mi = 0; mi < 4; mi++) {
                int r = a_row_base + mi * 16;
                int c16 = ks * 2 + a_c16_add;
                uint32_t ad = sb + r * 128 + (((uint32_t)(c16 ^ (r & 7))) << 4);
                LDSM4(a[mi][0], a[mi][1], a[mi][2], a[mi][3], ad);
            }
#pragma unroll
            for (int p = 0; p < 2; p++) {
                int r = b_row_base + p * 16;
                int c16 = ks * 2 + b_c16_add;
                uint32_t bd = sb + 16384 + r * 128 + (((uint32_t)(c16 ^ (r & 7))) << 4);
                LDSM4(b[p][0], b[p][1], b[p][2], b[p][3], bd);
            }
#pragma unroll
            for (int p = 0; p < 2; p++)
#pragma unroll
                for (int mi = 0; mi < 4; mi++) {
                    float* c0 = acc[mi][p][0];
                    float* c1 = acc[mi][p][1];
                    MMA16816(c0[0], c0[1], c0[2], c0[3],
                             a[mi][0], a[mi][1], a[mi][2], a[mi][3], b[p][0], b[p][1]);
                    MMA16816(c1[0], c1[1], c1[2], c1[3],
                             a[mi][0], a[mi][1], a[mi][2], a[mi][3], b[p][2], b[p][3]);
                }
        }
    }

    const int gid = lane >> 2, cpair = (lane & 3) * 2;
#pragma unroll
    for (int mi = 0; mi < 4; mi++)
#pragma unroll
        for (int p = 0; p < 2; p++)
#pragma unroll
            for (int jj = 0; jj < 2; jj++) {
                int rr = m0 + wm * 64 + mi * 16 + gid;
                int cc = n0 + wn * 32 + p * 16 + jj * 8 + cpair;
                const float* d = acc[mi][p][jj];
                *reinterpret_cast<float2*>(Cout + (size_t)rr * N + cc) = make_float2(d[0], d[1]);
                *reinterpret_cast<float2*>(Cout + (size_t)(rr + 8) * N + cc) = make_float2(d[2], d[3]);
            }
}

// ---------------- launch ----------------
extern "C" void kernel_launch(void* const* d_in, const int* in_sizes, int n_in,
                              void* d_out, int out_size) {
    const float* x  = (const float*)d_in[0];
    const int*   w0 = (const int*)  d_in[1];
    const int*   w1 = (const int*)  d_in[2];
    const int*   w2 = (const int*)  d_in[3];
    const float* s0 = (const float*)d_in[4];
    const float* s1 = (const float*)d_in[5];
    const float* s2 = (const float*)d_in[6];
    float* out = (float*)d_out;

    __half *px16, *pw0t, *pw1t, *pw2t, *ph16;
    cudaGetSymbolAddress((void**)&px16, d_x16);
    cudaGetSymbolAddress((void**)&pw0t, d_w0t);
    cudaGetSymbolAddress((void**)&pw1t, d_w1t);
    cudaGetSymbolAddress((void**)&pw2t, d_w2t);
    cudaGetSymbolAddress((void**)&ph16, d_h16);

    const size_t xTot = (size_t)M_DIM * H_DIM;
    convert_x_kernel<<<(unsigned)(xTot / 4 / 256), 256>>>(x);

    dequantT_kernel<<<dim3(I_DIM / 64, H_DIM / 64), 256>>>(w0, s0, pw0t, H_DIM, I_DIM, 1.0f);
    dequantT_kernel<<<dim3(I_DIM / 64, H_DIM / 64), 256>>>(w1, s1, pw1t, H_DIM, I_DIM, 1.0f);
    dequantT_kernel<<<dim3(H_DIM / 64, I_DIM / 64), 256>>>(w2, s2, pw2t, I_DIM, H_DIM, 64.0f);

    const int smem = 3 * 32768;   // 98304 B -> 2 CTAs/SM
    cudaFuncSetAttribute(gemm1_fused, cudaFuncAttributeMaxDynamicSharedMemorySize, smem);
    gemm1_fused<<<(M_DIM / 128) * (I_DIM / 64), 256, smem>>>(px16, pw0t, pw1t, ph16);

    cudaFuncSetAttribute(gemm2_plain, cudaFuncAttributeMaxDynamicSharedMemorySize, smem);
    gemm2_plain<<<(M_DIM / 128) * (H_DIM / 128), 256, smem>>>(ph16, pw2t, out);
}

// round 14
// speedup vs baseline: 1.0078x; 1.0078x over previous
#include <cuda_runtime.h>
#include <cuda_fp16.h>
#include <cstdint>

#define H_DIM 4096
#define I_DIM 14336
#define M_DIM 8192   // B*S
#define BSQ   128

// ---------------- static device scratch ----------------
__device__ __align__(16) __half d_x16[(size_t)M_DIM * H_DIM];   // x fp16 [M,H] K-major
__device__ __align__(16) __half d_w0t[(size_t)I_DIM * H_DIM];   // W0^T [I,H] K-major
__device__ __align__(16) __half d_w1t[(size_t)I_DIM * H_DIM];   // W1^T [I,H]
__device__ __align__(16) __half d_w2t[(size_t)H_DIM * I_DIM];   // W2^T [H,I] (x64)
__device__ __align__(16) __half d_h16[(size_t)M_DIM * I_DIM];   // h/64 fp16 [M,I]

// ---------------- PTX helpers ----------------
__device__ __forceinline__ uint32_t smem_u32(const void* p) {
    uint32_t a;
    asm("{ .reg .u64 t; cvta.to.shared.u64 t, %1; cvt.u32.u64 %0, t; }" : "=r"(a) : "l"(p));
    return a;
}
#define CP16(s, g)   asm volatile("cp.async.cg.shared.global [%0], [%1], 16;" :: "r"(s), "l"(g))
#define CP_COMMIT()  asm volatile("cp.async.commit_group;" ::: "memory")
template<int N> __device__ __forceinline__ void cp_wait() {
    asm volatile("cp.async.wait_group %0;" :: "n"(N) : "memory");
}
#define LDSM4(r0, r1, r2, r3, a) \
    asm volatile("ldmatrix.sync.aligned.m8n8.x4.shared.b16 {%0,%1,%2,%3}, [%4];" \
        : "=r"(r0), "=r"(r1), "=r"(r2), "=r"(r3) : "r"(a))
#define MMA16816(c0, c1, c2, c3, a0, a1, a2, a3, b0, b1) \
    asm volatile("mma.sync.aligned.m16n8k16.row.col.f32.f16.f16.f32 " \
        "{%0,%1,%2,%3}, {%4,%5,%6,%7}, {%8,%9}, {%0,%1,%2,%3};" \
        : "+f"(c0), "+f"(c1), "+f"(c2), "+f"(c3) \
        : "r"(a0), "r"(a1), "r"(a2), "r"(a3), "r"(b0), "r"(b1))

// =====================================================================================
// Fused prologue: one launch. Blocks [0, 32768): x fp32->fp16.
// Blocks [32768, 32768+3*14336): dequant+transpose of w0 / w1 / w2.
// =====================================================================================
__device__ __forceinline__ void dequantT_block(const int* __restrict__ w,
                                               const float* __restrict__ s,
                                               __half* __restrict__ out,
                                               int Kd, int Nd, float mult,
                                               int bn, int bk, int tid) {
    __shared__ __half tile[64][73];   // stride 73: conflict-free transpose
    const int n0 = bn * 64, k0 = bk * 64;
    const int sr = k0 / BSQ;
#pragma unroll
    for (int i = 0; i < 4; i++) {
        int v = tid + i * 256;
        int r = v >> 4, c4 = (v & 15) * 4;
        int4   wv = *reinterpret_cast<const int4*>(w + (size_t)(k0 + r) * Nd + n0 + c4);
        float4 sv = *reinterpret_cast<const float4*>(s + (size_t)sr * Nd + n0 + c4);
        tile[r][c4 + 0] = __float2half_rn((float)wv.x * sv.x * mult);
        tile[r][c4 + 1] = __float2half_rn((float)wv.y * sv.y * mult);
        tile[r][c4 + 2] = __float2half_rn((float)wv.z * sv.z * mult);
        tile[r][c4 + 3] = __float2half_rn((float)wv.w * sv.w * mult);
    }
    __syncthreads();
#pragma unroll
    for (int i = 0; i < 2; i++) {
        int v = tid + i * 256;
        int nr = v >> 3, kc = (v & 7) * 8;
        __align__(16) __half tmp[8];
#pragma unroll
        for (int e = 0; e < 8; e++) tmp[e] = tile[kc + e][nr];
        *reinterpret_cast<uint4*>(out + (size_t)(n0 + nr) * Kd + k0 + kc) =
            *reinterpret_cast<const uint4*>(tmp);
    }
}

__global__ __launch_bounds__(256)
void prologue_kernel(const float* __restrict__ x,
                     const int* __restrict__ w0, const float* __restrict__ s0,
                     const int* __restrict__ w1, const float* __restrict__ s1,
                     const int* __restrict__ w2, const float* __restrict__ s2) {
    const int tid = threadIdx.x;
    int b = blockIdx.x;
    constexpr int CONV_BLOCKS = (int)((size_t)M_DIM * H_DIM / 4 / 256);   // 32768
    constexpr int DQ01_BLOCKS = (I_DIM / 64) * (H_DIM / 64);              // 14336
    constexpr int DQ2_BLOCKS  = (H_DIM / 64) * (I_DIM / 64);              // 14336

    __half *px16, *pw0t, *pw1t, *pw2t;
    {
        // resolve symbol addresses device-side (compile-time known)
        px16 = d_x16; pw0t = d_w0t; pw1t = d_w1t; pw2t = d_w2t;
    }

    if (b < CONV_BLOCKS) {
        size_t base = ((size_t)b * 256 + tid) * 4;
        float4 v = *reinterpret_cast<const float4*>(x + base);
        __half2* o = reinterpret_cast<__half2*>(px16 + base);
        o[0] = __floats2half2_rn(v.x, v.y);
        o[1] = __floats2half2_rn(v.z, v.w);
        return;
    }
    b -= CONV_BLOCKS;
    if (b < DQ01_BLOCKS) {
        dequantT_block(w0, s0, pw0t, H_DIM, I_DIM, 1.0f, b % (I_DIM / 64), b / (I_DIM / 64), tid);
        return;
    }
    b -= DQ01_BLOCKS;
    if (b < DQ01_BLOCKS) {
        dequantT_block(w1, s1, pw1t, H_DIM, I_DIM, 1.0f, b % (I_DIM / 64), b / (I_DIM / 64), tid);
        return;
    }
    b -= DQ01_BLOCKS;
    dequantT_block(w2, s2, pw2t, I_DIM, H_DIM, 64.0f, b % (H_DIM / 64), b / (H_DIM / 64), tid);
}

// =====================================================================================
// GEMM1 fused: 256 thr, 2 CTAs/SM. CTA 128m x 64n. Warps 0-3 gate, 4-7 up (64x32 tiles).
// GROUP_M=32 swizzle. 3 stages x 32KB. Epilogue: smem exchange + silu -> fp16 h/64.
// =====================================================================================
__global__ __launch_bounds__(256, 2)
void gemm1_fused(const __half* __restrict__ A, const __half* __restrict__ B0,
                 const __half* __restrict__ B1, __half* __restrict__ Hout) {
    constexpr int K = H_DIM, N = I_DIM, STAGE = 32768, STAGES = 3;
    extern __shared__ char smem[];
    const uint32_t sbase = smem_u32(smem);
    const int tid = threadIdx.x, wid = tid >> 5, lane = tid & 31;
    const int t = wid >> 2;                  // 0=gate, 1=up
    const int w = wid & 3, wm = w & 1, wn = w >> 1;
    const int row_in = lane & 7, sel = lane >> 3;

    // GROUP_M=32 swizzle (A band-slice 33.5MB fits L2)
    const int per_band = 32 * (N >> 6);
    const int band = blockIdx.x / per_band, rem = blockIdx.x % per_band;
    const int m0 = (band * 32 + (rem & 31)) << 7;
    const int n0 = (rem >> 5) << 6;

    float acc[4][2][2][4];
#pragma unroll
    for (int mi = 0; mi < 4; mi++)
#pragma unroll
        for (int p = 0; p < 2; p++)
#pragma unroll
            for (int jj = 0; jj < 2; jj++)
#pragma unroll
                for (int e = 0; e < 4; e++) acc[mi][p][jj][e] = 0.0f;

    const char* Ab  = (const char*)(A  + (size_t)m0 * K);
    const char* B0b = (const char*)(B0 + (size_t)n0 * K);
    const char* B1b = (const char*)(B1 + (size_t)n0 * K);
    const size_t rowb = (size_t)K * 2;

    auto load_stage = [&](int c, int slot) {
        const uint32_t sb = sbase + slot * STAGE;
        const size_t koff = (size_t)c * 128;
#pragma unroll
        for (int j = 0; j < 4; j++) {
            int v = tid + j * 256, r = v >> 3, cs = v & 7, csw = cs ^ (r & 7);
            CP16(sb + r * 128 + csw * 16, Ab + (size_t)r * rowb + koff + cs * 16);
        }
#pragma unroll
        for (int j = 0; j < 4; j++) {
            int v = tid + j * 256, r = v >> 3, cs = v & 7, csw = cs ^ (r & 7);
            const char* src = ((r < 64) ? B0b + (size_t)r * rowb
                                        : B1b + (size_t)(r - 64) * rowb) + koff + cs * 16;
            CP16(sb + 16384 + r * 128 + csw * 16, src);
        }
    };

    const int NCH = K >> 6;   // 64
#pragma unroll
    for (int c = 0; c < STAGES - 1; c++) { load_stage(c, c); CP_COMMIT(); }

    const int a_row_base = wm * 64 + ((sel & 1) << 3) + row_in;
    const int a_c16_add  = sel >> 1;
    const int b_row_base = t * 64 + wn * 32 + ((sel >> 1) << 3) + row_in;
    const int b_c16_add  = sel & 1;

    int sc = 0, sl = STAGES - 1;
    for (int c = 0; c < NCH; c++) {
        cp_wait<STAGES - 2>();
        __syncthreads();
        const int lc = c + STAGES - 1;
        if (lc < NCH) load_stage(lc, sl);
        CP_COMMIT();
        if (++sl == STAGES) sl = 0;

        const uint32_t sb = sbase + sc * STAGE;
        if (++sc == STAGES) sc = 0;
#pragma unroll
        for (int ks = 0; ks < 4; ks++) {
            uint32_t a[4][4], b[2][4];
#pragma unroll
            for (int mi = 0; mi < 4; mi++) {
                int r = a_row_base + mi * 16;
                int c16 = ks * 2 + a_c16_add;
                uint32_t ad = sb + r * 128 + (((uint32_t)(c16 ^ (r & 7))) << 4);
                LDSM4(a[mi][0], a[mi][1], a[mi][2], a[mi][3], ad);
            }
#pragma unroll
            for (int p = 0; p < 2; p++) {
                int r = b_row_base + p * 16;
                int c16 = ks * 2 + b_c16_add;
                uint32_t bd = sb + 16384 + r * 128 + (((uint32_t)(c16 ^ (r & 7))) << 4);
                LDSM4(b[p][0], b[p][1], b[p][2], b[p][3], bd);
            }
#pragma unroll
            for (int p = 0; p < 2; p++)
#pragma unroll
                for (int mi = 0; mi < 4; mi++) {
                    float* c0 = acc[mi][p][0];
                    float* c1 = acc[mi][p][1];
                    MMA16816(c0[0], c0[1], c0[2], c0[3],
                             a[mi][0], a[mi][1], a[mi][2], a[mi][3], b[p][0], b[p][1]);
                    MMA16816(c1[0], c1[1], c1[2], c1[3],
                             a[mi][0], a[mi][1], a[mi][2], a[mi][3], b[p][2], b[p][3]);
                }
        }
    }

    // ---- epilogue: up warps publish 128x64 fp32 (stride 68), gate warps fuse ----
    cp_wait<0>();
    __syncthreads();
    constexpr int XS = 68;
    float* xch = (float*)smem;
    const int gid = lane >> 2, cpair = (lane & 3) * 2;
    if (t == 1) {
#pragma unroll
        for (int mi = 0; mi < 4; mi++)
#pragma unroll
            for (int p = 0; p < 2; p++)
#pragma unroll
                for (int jj = 0; jj < 2; jj++) {
                    int rr = wm * 64 + mi * 16 + gid;
                    int cc = wn * 32 + p * 16 + jj * 8 + cpair;
                    const float* d = acc[mi][p][jj];
                    *reinterpret_cast<float2*>(xch + rr * XS + cc) = make_float2(d[0], d[1]);
                    *reinterpret_cast<float2*>(xch + (rr + 8) * XS + cc) = make_float2(d[2], d[3]);
                }
    }
    __syncthreads();
    if (t == 0) {
#pragma unroll
        for (int mi = 0; mi < 4; mi++)
#pragma unroll
            for (int p = 0; p < 2; p++)
#pragma unroll
                for (int jj = 0; jj < 2; jj++) {
                    int rr = wm * 64 + mi * 16 + gid;
                    int cc = wn * 32 + p * 16 + jj * 8 + cpair;
                    const float* g = acc[mi][p][jj];
                    float2 u01 = *reinterpret_cast<const float2*>(xch + rr * XS + cc);
                    float2 u23 = *reinterpret_cast<const float2*>(xch + (rr + 8) * XS + cc);
                    float h0 = g[0] / (1.0f + __expf(-g[0])) * u01.x * 0.015625f;
                    float h1 = g[1] / (1.0f + __expf(-g[1])) * u01.y * 0.015625f;
                    float h2 = g[2] / (1.0f + __expf(-g[2])) * u23.x * 0.015625f;
                    float h3 = g[3] / (1.0f + __expf(-g[3])) * u23.y * 0.015625f;
                    *reinterpret_cast<__half2*>(Hout + (size_t)(m0 + rr) * N + n0 + cc) =
                        __floats2half2_rn(h0, h1);
                    *reinterpret_cast<__half2*>(Hout + (size_t)(m0 + rr + 8) * N + n0 + cc) =
                        __floats2half2_rn(h2, h3);
                }
    }
}

// =====================================================================================
// GEMM2: 256 thr, 2 CTAs/SM. CTA 128m x 128n, warps 2x4 of 64x32. out fp32. GROUP_M=16.
// =====================================================================================
__global__ __launch_bounds__(256, 2)
void gemm2_plain(const __half* __restrict__ A, const __half* __restrict__ B,
                 float* __restrict__ Cout) {
    constexpr int K = I_DIM, N = H_DIM, STAGE = 32768, STAGES = 3;
    extern __shared__ char smem[];
    const uint32_t sbase = smem_u32(smem);
    const int tid = threadIdx.x, wid = tid >> 5, lane = tid & 31;
    const int wm = wid & 1, wn = wid >> 1;
    const int row_in = lane & 7, sel = lane >> 3;

    const int per_band = 16 * (N >> 7);
    const int band = blockIdx.x / per_band, rem = blockIdx.x % per_band;
    const int m0 = (band * 16 + (rem & 15)) << 7;
    const int n0 = (rem >> 4) << 7;

    float acc[4][2][2][4];
#pragma unroll
    for (int mi = 0; mi < 4; mi++)
#pragma unroll
        for (int p = 0; p < 2; p++)
#pragma unroll
            for (int jj = 0; jj < 2; jj++)
#pragma unroll
                for (int e = 0; e < 4; e++) acc[mi][p][jj][e] = 0.0f;

    const char* Ab = (const char*)(A + (size_t)m0 * K);
    const char* Bb = (const char*)(B + (size_t)n0 * K);
    const size_t rowb = (size_t)K * 2;

    auto load_stage = [&](int c, int slot) {
        const uint32_t sb = sbase + slot * STAGE;
        const size_t koff = (size_t)c * 128;
#pragma unroll
        for (int j = 0; j < 4; j++) {
            int v = tid + j * 256, r = v >> 3, cs = v & 7, csw = cs ^ (r & 7);
            CP16(sb + r * 128 + csw * 16, Ab + (size_t)r * rowb + koff + cs * 16);
        }
#pragma unroll
        for (int j = 0; j < 4; j++) {
            int v = tid + j * 256, r = v >> 3, cs = v & 7, csw = cs ^ (r & 7);
            CP16(sb + 16384 + r * 128 + csw * 16, Bb + (size_t)r * rowb + koff + cs * 16);
        }
    };

    const int NCH = K >> 6;   // 224
#pragma unroll
    for (int c = 0; c < STAGES - 1; c++) { load_stage(c, c); CP_COMMIT(); }

    const int a_row_base = wm * 64 + ((sel & 1) << 3) + row_in;
    const int a_c16_add  = sel >> 1;
    const int b_row_base = wn * 32 + ((sel >> 1) << 3) + row_in;
    const int b_c16_add  = sel & 1;

    int sc = 0, sl = STAGES - 1;
    for (int c = 0; c < NCH; c++) {
        cp_wait<STAGES - 2>();
        __syncthreads();
        const int lc = c + STAGES - 1;
        if (lc < NCH) load_stage(lc, sl);
        CP_COMMIT();
        if (++sl == STAGES) sl = 0;

        const uint32_t sb = sbase + sc * STAGE;
        if (++sc == STAGES) sc = 0;
#pragma unroll
        for (int ks = 0; ks < 4; ks++) {
            uint32_t a[4][4], b[2][4];
#pragma unroll
            for (int mi = 0; mi < 4; mi++) {
                int r = a_row_base + mi * 16;
                int c16 = ks * 2 + a_c16_add;
                uint32_t ad = sb + r * 128 + (((uint32_t)(c16 ^ (r & 7))) << 4);
                LDSM4(a[mi][0], a[mi][1], a[mi][2], a[mi][3], ad);
            }
#pragma unroll
            for (int p = 0; p < 2; p++) {
                int r = b_row_base + p * 16;
                int c16 = ks * 2 + b_c16_add;
                uint32_t bd = sb + 16384 + r * 128 + (((uint32_t)(c16 ^ (r & 7))) << 4);
                LDSM4(b[p][0], b[p][1], b[p][2], b[p][3], bd);
            }
#pragma unroll
            for (int p = 0; p < 2; p++)
#pragma unroll
                for (int mi = 0; mi < 4; mi++) {
                    float* c0 = acc[mi][p][0];
                    float* c1 = acc[mi][p][1];
                    MMA16816(c0[0], c0[1], c0[2], c0[3],
                             a[mi][0], a[mi][1], a[mi][2], a[mi][3], b[p][0], b[p][1]);
                    MMA16816(c1[0], c1[1], c1[2], c1[3],
                             a[mi][0], a[mi][1], a[mi][2], a[mi][3], b[p][2], b[p][3]);
                }
        }
    }

    const int gid = lane >> 2, cpair = (lane & 3) * 2;
#pragma unroll
    for (int mi = 0; mi < 4; mi++)
#pragma unroll
        for (int p = 0; p < 2; p++)
#pragma unroll
            for (int jj = 0; jj < 2; jj++) {
                int rr = m0 + wm * 64 + mi * 16 + gid;
                int cc = n0 + wn * 32 + p * 16 + jj * 8 + cpair;
                const float* d = acc[mi][p][jj];
                *reinterpret_cast<float2*>(Cout + (size_t)rr * N + cc) = make_float2(d[0], d[1]);
                *reinterpret_cast<float2*>(Cout + (size_t)(rr + 8) * N + cc) = make_float2(d[2], d[3]);
            }
}

// ---------------- launch ----------------
extern "C" void kernel_launch(void* const* d_in, const int* in_sizes, int n_in,
                              void* d_out, int out_size) {
    const float* x  = (const float*)d_in[0];
    const int*   w0 = (const int*)  d_in[1];
    const int*   w1 = (const int*)  d_in[2];
    const int*   w2 = (const int*)  d_in[3];
    const float* s0 = (const float*)d_in[4];
    const float* s1 = (const float*)d_in[5];
    const float* s2 = (const float*)d_in[6];
    float* out = (float*)d_out;

    __half *px16, *pw0t, *pw1t, *ph16;
    cudaGetSymbolAddress((void**)&px16, d_x16);
    cudaGetSymbolAddress((void**)&pw0t, d_w0t);
    cudaGetSymbolAddress((void**)&pw1t, d_w1t);
    cudaGetSymbolAddress((void**)&ph16, d_h16);
    __half *pw2t;
    cudaGetSymbolAddress((void**)&pw2t, d_w2t);

    // fused prologue: convert x + dequant/transpose all three weights, one launch
    const unsigned CONV_BLOCKS = (unsigned)((size_t)M_DIM * H_DIM / 4 / 256);  // 32768
    const unsigned DQ_BLOCKS = (I_DIM / 64) * (H_DIM / 64);                    // 14336
    prologue_kernel<<<CONV_BLOCKS + 3 * DQ_BLOCKS, 256>>>(x, w0, s0, w1, s1, w2, s2);

    const int smem = 3 * 32768;   // 98304 B -> 2 CTAs/SM
    cudaFuncSetAttribute(gemm1_fused, cudaFuncAttributeMaxDynamicSharedMemorySize, smem);
    gemm1_fused<<<(M_DIM / 128) * (I_DIM / 64), 256, smem>>>(px16, pw0t, pw1t, ph16);

    cudaFuncSetAttribute(gemm2_plain, cudaFuncAttributeMaxDynamicSharedMemorySize, smem);
    gemm2_plain<<<(M_DIM / 128) * (H_DIM / 128), 256, smem>>>(ph16, pw2t, out);
}

// round 15
// speedup vs baseline: 1.0405x; 1.0325x over previous
#include <cuda_runtime.h>
#include <cuda_fp16.h>
#include <cstdint>

#define H_DIM 4096
#define I_DIM 14336
#define M_DIM 8192   // B*S
#define BSQ   128

// ---------------- static device scratch ----------------
__device__ __align__(16) __half d_x16[(size_t)M_DIM * H_DIM];   // x fp16 [M,H] K-major
__device__ __align__(16) __half d_w0t[(size_t)I_DIM * H_DIM];   // W0^T [I,H] K-major
__device__ __align__(16) __half d_w1t[(size_t)I_DIM * H_DIM];   // W1^T [I,H]
__device__ __align__(16) __half d_w2t[(size_t)H_DIM * I_DIM];   // W2^T [H,I] (x64)
__device__ __align__(16) __half d_h16[(size_t)M_DIM * I_DIM];   // h/64 fp16 [M,I]

// ---------------- PTX helpers ----------------
__device__ __forceinline__ uint32_t smem_u32(const void* p) {
    uint32_t a;
    asm("{ .reg .u64 t; cvta.to.shared.u64 t, %1; cvt.u32.u64 %0, t; }" : "=r"(a) : "l"(p));
    return a;
}
#define CP16(s, g)   asm volatile("cp.async.cg.shared.global [%0], [%1], 16;" :: "r"(s), "l"(g))
#define CP_COMMIT()  asm volatile("cp.async.commit_group;" ::: "memory")
template<int N> __device__ __forceinline__ void cp_wait() {
    asm volatile("cp.async.wait_group %0;" :: "n"(N) : "memory");
}
#define LDSM4(r0, r1, r2, r3, a) \
    asm volatile("ldmatrix.sync.aligned.m8n8.x4.shared.b16 {%0,%1,%2,%3}, [%4];" \
        : "=r"(r0), "=r"(r1), "=r"(r2), "=r"(r3) : "r"(a))
#define MMA16816(c0, c1, c2, c3, a0, a1, a2, a3, b0, b1) \
    asm volatile("mma.sync.aligned.m16n8k16.row.col.f32.f16.f16.f32 " \
        "{%0,%1,%2,%3}, {%4,%5,%6,%7}, {%8,%9}, {%0,%1,%2,%3};" \
        : "+f"(c0), "+f"(c1), "+f"(c2), "+f"(c3) \
        : "r"(a0), "r"(a1), "r"(a2), "r"(a3), "r"(b0), "r"(b1))

// ---------------- dequant+transpose tile worker (dynamic smem) ----------------
__device__ __forceinline__ void dequantT_block_dyn(char* smem,
                                                   const int* __restrict__ w,
                                                   const float* __restrict__ s,
                                                   __half* __restrict__ out,
                                                   int Kd, int Nd, float mult,
                                                   int bn, int bk, int tid) {
    __half (*tile)[73] = (__half(*)[73])smem;   // stride 73: conflict-free transpose
    const int n0 = bn * 64, k0 = bk * 64;
    const int sr = k0 / BSQ;
#pragma unroll
    for (int i = 0; i < 4; i++) {
        int v = tid + i * 256;
        int r = v >> 4, c4 = (v & 15) * 4;
        int4   wv = *reinterpret_cast<const int4*>(w + (size_t)(k0 + r) * Nd + n0 + c4);
        float4 sv = *reinterpret_cast<const float4*>(s + (size_t)sr * Nd + n0 + c4);
        tile[r][c4 + 0] = __float2half_rn((float)wv.x * sv.x * mult);
        tile[r][c4 + 1] = __float2half_rn((float)wv.y * sv.y * mult);
        tile[r][c4 + 2] = __float2half_rn((float)wv.z * sv.z * mult);
        tile[r][c4 + 3] = __float2half_rn((float)wv.w * sv.w * mult);
    }
    __syncthreads();
#pragma unroll
    for (int i = 0; i < 2; i++) {
        int v = tid + i * 256;
        int nr = v >> 3, kc = (v & 7) * 8;
        __align__(16) __half tmp[8];
#pragma unroll
        for (int e = 0; e < 8; e++) tmp[e] = tile[kc + e][nr];
        *reinterpret_cast<uint4*>(out + (size_t)(n0 + nr) * Kd + k0 + kc) =
            *reinterpret_cast<const uint4*>(tmp);
    }
}

// =====================================================================================
// Prologue: one launch. Blocks [0, 32768): x fp32->fp16.
// Blocks [32768, 32768+2*14336): dequant+transpose of w0 / w1. (w2 hidden in GEMM1.)
// =====================================================================================
__global__ __launch_bounds__(256)
void prologue_kernel(const float* __restrict__ x,
                     const int* __restrict__ w0, const float* __restrict__ s0,
                     const int* __restrict__ w1, const float* __restrict__ s1) {
    __shared__ char smem[64 * 73 * 2 + 16];
    const int tid = threadIdx.x;
    int b = blockIdx.x;
    constexpr int CONV_BLOCKS = (int)((size_t)M_DIM * H_DIM / 4 / 256);   // 32768
    constexpr int DQ01_BLOCKS = (I_DIM / 64) * (H_DIM / 64);              // 14336

    if (b < CONV_BLOCKS) {
        size_t base = ((size_t)b * 256 + tid) * 4;
        float4 v = *reinterpret_cast<const float4*>(x + base);
        __half2* o = reinterpret_cast<__half2*>(d_x16 + base);
        o[0] = __floats2half2_rn(v.x, v.y);
        o[1] = __floats2half2_rn(v.z, v.w);
        return;
    }
    b -= CONV_BLOCKS;
    if (b < DQ01_BLOCKS) {
        dequantT_block_dyn(smem, w0, s0, d_w0t, H_DIM, I_DIM, 1.0f,
                           b % (I_DIM / 64), b / (I_DIM / 64), tid);
        return;
    }
    b -= DQ01_BLOCKS;
    dequantT_block_dyn(smem, w1, s1, d_w1t, H_DIM, I_DIM, 1.0f,
                       b % (I_DIM / 64), b / (I_DIM / 64), tid);
}

// =====================================================================================
// GEMM1 fused + hidden w2 dequant. 256 thr, 2 CTAs/SM.
// Blocks: first 2*14336 interleaved (even -> w2 dequant tile, odd -> GEMM tile);
// remaining blocks -> GEMM tiles. GEMM: CTA 128m x 64n, warps 0-3 gate / 4-7 up,
// GROUP_M=32 swizzle, 3 stages x 32KB. Epilogue: smem exchange + silu -> fp16 h/64.
// =====================================================================================
__global__ __launch_bounds__(256, 2)
void gemm1_fused(const __half* __restrict__ A, const __half* __restrict__ B0,
                 const __half* __restrict__ B1, __half* __restrict__ Hout,
                 const int* __restrict__ w2, const float* __restrict__ s2) {
    constexpr int K = H_DIM, N = I_DIM, STAGE = 32768, STAGES = 3;
    constexpr int DQ2 = (H_DIM / 64) * (I_DIM / 64);   // 14336 w2 tiles
    extern __shared__ char smem[];
    const int tid = threadIdx.x;

    int bx = blockIdx.x;
    int tile_idx;
    if (bx < 2 * DQ2) {
        if ((bx & 1) == 0) {   // w2 dequant tile, runs concurrent with early GEMM waves
            int b = bx >> 1;
            dequantT_block_dyn(smem, w2, s2, d_w2t, I_DIM, H_DIM, 64.0f,
                               b % (H_DIM / 64), b / (H_DIM / 64), tid);
            return;
        }
        tile_idx = bx >> 1;
    } else {
        tile_idx = bx - DQ2;
    }

    const uint32_t sbase = smem_u32(smem);
    const int wid = tid >> 5, lane = tid & 31;
    const int t = wid >> 2;                  // 0=gate, 1=up
    const int w = wid & 3, wm = w & 1, wn = w >> 1;
    const int row_in = lane & 7, sel = lane >> 3;

    // GROUP_M=32 swizzle (A band-slice 33.5MB fits L2)
    const int per_band = 32 * (N >> 6);
    const int band = tile_idx / per_band, rem = tile_idx % per_band;
    const int m0 = (band * 32 + (rem & 31)) << 7;
    const int n0 = (rem >> 5) << 6;

    float acc[4][2][2][4];
#pragma unroll
    for (int mi = 0; mi < 4; mi++)
#pragma unroll
        for (int p = 0; p < 2; p++)
#pragma unroll
            for (int jj = 0; jj < 2; jj++)
#pragma unroll
                for (int e = 0; e < 4; e++) acc[mi][p][jj][e] = 0.0f;

    const char* Ab  = (const char*)(A  + (size_t)m0 * K);
    const char* B0b = (const char*)(B0 + (size_t)n0 * K);
    const char* B1b = (const char*)(B1 + (size_t)n0 * K);
    const size_t rowb = (size_t)K * 2;

    auto load_stage = [&](int c, int slot) {
        const uint32_t sb = sbase + slot * STAGE;
        const size_t koff = (size_t)c * 128;
#pragma unroll
        for (int j = 0; j < 4; j++) {
            int v = tid + j * 256, r = v >> 3, cs = v & 7, csw = cs ^ (r & 7);
            CP16(sb + r * 128 + csw * 16, Ab + (size_t)r * rowb + koff + cs * 16);
        }
#pragma unroll
        for (int j = 0; j < 4; j++) {
            int v = tid + j * 256, r = v >> 3, cs = v & 7, csw = cs ^ (r & 7);
            const char* src = ((r < 64) ? B0b + (size_t)r * rowb
                                        : B1b + (size_t)(r - 64) * rowb) + koff + cs * 16;
            CP16(sb + 16384 + r * 128 + csw * 16, src);
        }
    };

    const int NCH = K >> 6;   // 64
#pragma unroll
    for (int c = 0; c < STAGES - 1; c++) { load_stage(c, c); CP_COMMIT(); }

    const int a_row_base = wm * 64 + ((sel & 1) << 3) + row_in;
    const int a_c16_add  = sel >> 1;
    const int b_row_base = t * 64 + wn * 32 + ((sel >> 1) << 3) + row_in;
    const int b_c16_add  = sel & 1;

    auto do_ks = [&](uint32_t sb, int ks) {
        uint32_t a[4][4], b[2][4];
#pragma unroll
        for (int mi = 0; mi < 4; mi++) {
            int r = a_row_base + mi * 16;
            int c16 = ks * 2 + a_c16_add;
            uint32_t ad = sb + r * 128 + (((uint32_t)(c16 ^ (r & 7))) << 4);
            LDSM4(a[mi][0], a[mi][1], a[mi][2], a[mi][3], ad);
        }
#pragma unroll
        for (int p = 0; p < 2; p++) {
            int r = b_row_base + p * 16;
            int c16 = ks * 2 + b_c16_add;
            uint32_t bd = sb + 16384 + r * 128 + (((uint32_t)(c16 ^ (r & 7))) << 4);
            LDSM4(b[p][0], b[p][1], b[p][2], b[p][3], bd);
        }
#pragma unroll
        for (int p = 0; p < 2; p++)
#pragma unroll
            for (int mi = 0; mi < 4; mi++) {
                float* c0 = acc[mi][p][0];
                float* c1 = acc[mi][p][1];
                MMA16816(c0[0], c0[1], c0[2], c0[3],
                         a[mi][0], a[mi][1], a[mi][2], a[mi][3], b[p][0], b[p][1]);
                MMA16816(c1[0], c1[1], c1[2], c1[3],
                         a[mi][0], a[mi][1], a[mi][2], a[mi][3], b[p][2], b[p][3]);
            }
    };

    int sc = 0, sl = STAGES - 1;
    for (int c = 0; c < NCH; c++) {
        cp_wait<STAGES - 2>();
        __syncthreads();
        const uint32_t sb = sbase + sc * STAGE;
        if (++sc == STAGES) sc = 0;

        do_ks(sb, 0);                         // MMA burst first...
        const int lc = c + STAGES - 1;        // ...then issue next stage's loads
        if (lc < NCH) load_stage(lc, sl);
        CP_COMMIT();
        if (++sl == STAGES) sl = 0;
#pragma unroll
        for (int ks = 1; ks < 4; ks++) do_ks(sb, ks);
    }

    // ---- epilogue: up warps publish 128x64 fp32 (stride 68), gate warps fuse ----
    cp_wait<0>();
    __syncthreads();
    constexpr int XS = 68;
    float* xch = (float*)smem;
    const int gid = lane >> 2, cpair = (lane & 3) * 2;
    if (t == 1) {
#pragma unroll
        for (int mi = 0; mi < 4; mi++)
#pragma unroll
            for (int p = 0; p < 2; p++)
#pragma unroll
                for (int jj = 0; jj < 2; jj++) {
                    int rr = wm * 64 + mi * 16 + gid;
                    int cc = wn * 32 + p * 16 + jj * 8 + cpair;
                    const float* d = acc[mi][p][jj];
                    *reinterpret_cast<float2*>(xch + rr * XS + cc) = make_float2(d[0], d[1]);
                    *reinterpret_cast<float2*>(xch + (rr + 8) * XS + cc) = make_float2(d[2], d[3]);
                }
    }
    __syncthreads();
    if (t == 0) {
#pragma unroll
        for (int mi = 0; mi < 4; mi++)
#pragma unroll
            for (int p = 0; p < 2; p++)
#pragma unroll
                for (int jj = 0; jj < 2; jj++) {
                    int rr = wm * 64 + mi * 16 + gid;
                    int cc = wn * 32 + p * 16 + jj * 8 + cpair;
                    const float* g = acc[mi][p][jj];
                    float2 u01 = *reinterpret_cast<const float2*>(xch + rr * XS + cc);
                    float2 u23 = *reinterpret_cast<const float2*>(xch + (rr + 8) * XS + cc);
                    float h0 = g[0] / (1.0f + __expf(-g[0])) * u01.x * 0.015625f;
                    float h1 = g[1] / (1.0f + __expf(-g[1])) * u01.y * 0.015625f;
                    float h2 = g[2] / (1.0f + __expf(-g[2])) * u23.x * 0.015625f;
                    float h3 = g[3] / (1.0f + __expf(-g[3])) * u23.y * 0.015625f;
                    *reinterpret_cast<__half2*>(Hout + (size_t)(m0 + rr) * N + n0 + cc) =
                        __floats2half2_rn(h0, h1);
                    *reinterpret_cast<__half2*>(Hout + (size_t)(m0 + rr + 8) * N + n0 + cc) =
                        __floats2half2_rn(h2, h3);
                }
    }
}

// =====================================================================================
// GEMM2: 256 thr, 2 CTAs/SM. CTA 128m x 128n, warps 2x4 of 64x32. out fp32. GROUP_M=16.
// =====================================================================================
__global__ __launch_bounds__(256, 2)
void gemm2_plain(const __half* __restrict__ A, const __half* __restrict__ B,
                 float* __restrict__ Cout) {
    constexpr int K = I_DIM, N = H_DIM, STAGE = 32768, STAGES = 3;
    extern __shared__ char smem[];
    const uint32_t sbase = smem_u32(smem);
    const int tid = threadIdx.x, wid = tid >> 5, lane = tid & 31;
    const int wm = wid & 1, wn = wid >> 1;
    const int row_in = lane & 7, sel = lane >> 3;

    const int per_band = 16 * (N >> 7);
    const int band = blockIdx.x / per_band, rem = blockIdx.x % per_band;
    const int m0 = (band * 16 + (rem & 15)) << 7;
    const int n0 = (rem >> 4) << 7;

    float acc[4][2][2][4];
#pragma unroll
    for (int mi = 0; mi < 4; mi++)
#pragma unroll
        for (int p = 0; p < 2; p++)
#pragma unroll
            for (int jj = 0; jj < 2; jj++)
#pragma unroll
                for (int e = 0; e < 4; e++) acc[mi][p][jj][e] = 0.0f;

    const char* Ab = (const char*)(A + (size_t)m0 * K);
    const char* Bb = (const char*)(B + (size_t)n0 * K);
    const size_t rowb = (size_t)K * 2;

    auto load_stage = [&](int c, int slot) {
        const uint32_t sb = sbase + slot * STAGE;
        const size_t koff = (size_t)c * 128;
#pragma unroll
        for (int j = 0; j < 4; j++) {
            int v = tid + j * 256, r = v >> 3, cs = v & 7, csw = cs ^ (r & 7);
            CP16(sb + r * 128 + csw * 16, Ab + (size_t)r * rowb + koff + cs * 16);
        }
#pragma unroll
        for (int j = 0; j < 4; j++) {
            int v = tid + j * 256, r = v >> 3, cs = v & 7, csw = cs ^ (r & 7);
            CP16(sb + 16384 + r * 128 + csw * 16, Bb + (size_t)r * rowb + koff + cs * 16);
        }
    };

    const int NCH = K >> 6;   // 224
#pragma unroll
    for (int c = 0; c < STAGES - 1; c++) { load_stage(c, c); CP_COMMIT(); }

    const int a_row_base = wm * 64 + ((sel & 1) << 3) + row_in;
    const int a_c16_add  = sel >> 1;
    const int b_row_base = wn * 32 + ((sel >> 1) << 3) + row_in;
    const int b_c16_add  = sel & 1;

    auto do_ks = [&](uint32_t sb, int ks) {
        uint32_t a[4][4], b[2][4];
#pragma unroll
        for (int mi = 0; mi < 4; mi++) {
            int r = a_row_base + mi * 16;
            int c16 = ks * 2 + a_c16_add;
            uint32_t ad = sb + r * 128 + (((uint32_t)(c16 ^ (r & 7))) << 4);
            LDSM4(a[mi][0], a[mi][1], a[mi][2], a[mi][3], ad);
        }
#pragma unroll
        for (int p = 0; p < 2; p++) {
            int r = b_row_base + p * 16;
            int c16 = ks * 2 + b_c16_add;
            uint32_t bd = sb + 16384 + r * 128 + (((uint32_t)(c16 ^ (r & 7))) << 4);
            LDSM4(b[p][0], b[p][1], b[p][2], b[p][3], bd);
        }
#pragma unroll
        for (int p = 0; p < 2; p++)
#pragma unroll
            for (int mi = 0; mi < 4; mi++) {
                float* c0 = acc[mi][p][0];
                float* c1 = acc[mi][p][1];
                MMA16816(c0[0], c0[1], c0[2], c0[3],
                         a[mi][0], a[mi][1], a[mi][2], a[mi][3], b[p][0], b[p][1]);
                MMA16816(c1[0], c1[1], c1[2], c1[3],
                         a[mi][0], a[mi][1], a[mi][2], a[mi][3], b[p][2], b[p][3]);
            }
    };

    int sc = 0, sl = STAGES - 1;
    for (int c = 0; c < NCH; c++) {
        cp_wait<STAGES - 2>();
        __syncthreads();
        const uint32_t sb = sbase + sc * STAGE;
        if (++sc == STAGES) sc = 0;

        do_ks(sb, 0);
        const int lc = c + STAGES - 1;
        if (lc < NCH) load_stage(lc, sl);
        CP_COMMIT();
        if (++sl == STAGES) sl = 0;
#pragma unroll
        for (int ks = 1; ks < 4; ks++) do_ks(sb, ks);
    }

    const int gid = lane >> 2, cpair = (lane & 3) * 2;
#pragma unroll
    for (int mi = 0; mi < 4; mi++)
#pragma unroll
        for (int p = 0; p < 2; p++)
#pragma unroll
            for (int jj = 0; jj < 2; jj++) {
                int rr = m0 + wm * 64 + mi * 16 + gid;
                int cc = n0 + wn * 32 + p * 16 + jj * 8 + cpair;
                const float* d = acc[mi][p][jj];
                *reinterpret_cast<float2*>(Cout + (size_t)rr * N + cc) = make_float2(d[0], d[1]);
                *reinterpret_cast<float2*>(Cout + (size_t)(rr + 8) * N + cc) = make_float2(d[2], d[3]);
            }
}

// ---------------- launch ----------------
extern "C" void kernel_launch(void* const* d_in, const int* in_sizes, int n_in,
                              void* d_out, int out_size) {
    const float* x  = (const float*)d_in[0];
    const int*   w0 = (const int*)  d_in[1];
    const int*   w1 = (const int*)  d_in[2];
    const int*   w2 = (const int*)  d_in[3];
    const float* s0 = (const float*)d_in[4];
    const float* s1 = (const float*)d_in[5];
    const float* s2 = (const float*)d_in[6];
    float* out = (float*)d_out;

    __half *px16, *pw0t, *pw1t, *pw2t, *ph16;
    cudaGetSymbolAddress((void**)&px16, d_x16);
    cudaGetSymbolAddress((void**)&pw0t, d_w0t);
    cudaGetSymbolAddress((void**)&pw1t, d_w1t);
    cudaGetSymbolAddress((void**)&pw2t, d_w2t);
    cudaGetSymbolAddress((void**)&ph16, d_h16);

    // prologue: convert x + dequant/transpose w0,w1 (w2 hidden inside GEMM1)
    const unsigned CONV_BLOCKS = (unsigned)((size_t)M_DIM * H_DIM / 4 / 256);  // 32768
    const unsigned DQ_BLOCKS = (I_DIM / 64) * (H_DIM / 64);                    // 14336
    prologue_kernel<<<CONV_BLOCKS + 2 * DQ_BLOCKS, 256>>>(x, w0, s0, w1, s1);

    const int smem = 3 * 32768;   // 98304 B -> 2 CTAs/SM
    // GEMM1 grid: 14336 GEMM tiles + 14336 w2-dequant tiles, interleaved up front
    cudaFuncSetAttribute(gemm1_fused, cudaFuncAttributeMaxDynamicSharedMemorySize, smem);
    gemm1_fused<<<2 * DQ_BLOCKS + ((M_DIM / 128) * (I_DIM / 64) - DQ_BLOCKS), 256, smem>>>(
        px16, pw0t, pw1t, ph16, w2, s2);

    cudaFuncSetAttribute(gemm2_plain, cudaFuncAttributeMaxDynamicSharedMemorySize, smem);
    gemm2_plain<<<(M_DIM / 128) * (H_DIM / 128), 256, smem>>>(ph16, pw2t, out);
}